// round 5
// baseline (speedup 1.0000x reference)
#include <cuda_runtime.h>
#include <cuda_bf16.h>
#include <mma.h>
#include <cstddef>

using namespace nvcuda;

// Problem constants
#define Bc 4
#define Sc 1024
#define Dc 1024
#define Hc 16
#define DKc 64
#define DVc 64
#define Mc (Bc * Sc)        // 4096
#define HDc (Hc * DKc)      // 1024
#define QP_ELEMS (Mc * HDc) // 4,194,304 (also [B,H,S,64] count)

// ---------------- Static device scratch (hi/lo bf16 planes) ----------------
__device__ __nv_bfloat16 g_qh[Mc * Dc],  g_ql[Mc * Dc];
__device__ __nv_bfloat16 g_kh[Mc * Dc],  g_kl[Mc * Dc];
__device__ __nv_bfloat16 g_vh[Mc * Dc],  g_vl[Mc * Dc];
__device__ __nv_bfloat16 g_Wqh[Dc * HDc], g_Wql[Dc * HDc];
__device__ __nv_bfloat16 g_Wkh[Dc * HDc], g_Wkl[Dc * HDc];
__device__ __nv_bfloat16 g_Wvh[Dc * HDc], g_Wvl[Dc * HDc];
__device__ __nv_bfloat16 g_Woh[Dc * HDc], g_Wol[Dc * HDc];
__device__ __nv_bfloat16 g_Qph[QP_ELEMS], g_Qpl[QP_ELEMS];   // [B,H,S,64]
__device__ __nv_bfloat16 g_Kph[QP_ELEMS], g_Kpl[QP_ELEMS];
__device__ __nv_bfloat16 g_Vph[QP_ELEMS], g_Vpl[QP_ELEMS];
__device__ __nv_bfloat16 g_ctxh[Mc * HDc], g_ctxl[Mc * HDc]; // concat layout
__device__ float g_obuf[Mc * Dc];
__device__ float g_attn_fb[(size_t)Bc * Hc * Sc * Sc];
__device__ int   g_mask_mode;

// bf16 fragments (16x16x16)
using bfrag_a  = wmma::fragment<wmma::matrix_a, 16, 16, 16, __nv_bfloat16, wmma::row_major>;
using bfrag_b  = wmma::fragment<wmma::matrix_b, 16, 16, 16, __nv_bfloat16, wmma::row_major>;
using bfrag_bc = wmma::fragment<wmma::matrix_b, 16, 16, 16, __nv_bfloat16, wmma::col_major>;
using bfrag_c  = wmma::fragment<wmma::accumulator, 16, 16, 16, float>;

__device__ __forceinline__ void cvt_store4(__nv_bfloat16* dh, __nv_bfloat16* dl, float4 v) {
    float a[4] = {v.x, v.y, v.z, v.w};
#pragma unroll
    for (int j = 0; j < 4; j++) {
        __nv_bfloat16 h = __float2bfloat16(a[j]);
        dh[j] = h;
        dl[j] = __float2bfloat16(a[j] - __bfloat162float(h));
    }
}

// ---------------------------------------------------------------------------
// fp32 -> hi/lo bf16 planes (grid-stride, float4)
// ---------------------------------------------------------------------------
__global__ __launch_bounds__(256)
void cvt_pair_kernel(const float4* __restrict__ src, __nv_bfloat16* __restrict__ hi,
                     __nv_bfloat16* __restrict__ lo, int n4) {
    for (int i = blockIdx.x * 256 + threadIdx.x; i < n4; i += gridDim.x * 256)
        cvt_store4(hi + (size_t)i * 4, lo + (size_t)i * 4, src[i]);
}

// ---------------------------------------------------------------------------
// Mask dtype detection
// ---------------------------------------------------------------------------
__global__ void detect_mask_kernel(const unsigned int* __restrict__ m) {
    bool allint = true, allfloat = true;
    for (int i = 0; i < 1024; i++) {
        unsigned int w = m[i];
        if (w > 1u) allint = false;
        if (w != 0u && w != 0x3F800000u) allfloat = false;
    }
    g_mask_mode = allint ? 0 : (allfloat ? 2 : 1);
}

// ---------------------------------------------------------------------------
// Pure-bf16-plane split GEMM: C = A[*,1024] @ W[1024,N] (+bias), 3-term split.
// BM=128, BN=64, BK=16, double-buffered, register prefetch, NO conversions.
// OUTMODE 0: fp32 row-major [*,1024] (+bias)              (out-proj)
// OUTMODE 1: hi/lo planes to [B,H,S,64], head=blockIdx.x (+bias)  (projections)
// ---------------------------------------------------------------------------
template <int OUTMODE>
__global__ __launch_bounds__(256)
void gemm_planes(const __nv_bfloat16* __restrict__ Ah, const __nv_bfloat16* __restrict__ Al,
                 const __nv_bfloat16* __restrict__ Wh, const __nv_bfloat16* __restrict__ Wl,
                 const float* __restrict__ bias, float* __restrict__ Cf,
                 __nv_bfloat16* __restrict__ Ch, __nv_bfloat16* __restrict__ Cl, int N) {
    constexpr int LDA = 24;    // bf16 elems
    constexpr int LDW = 72;
    constexpr int LDST = 68;   // fp32 staging

    __shared__ __align__(16) char buf[34816];
    __nv_bfloat16* Ahi = (__nv_bfloat16*)buf;        // [2][128][24]
    __nv_bfloat16* Alo = Ahi + 2 * 128 * LDA;
    __nv_bfloat16* Whi = Alo + 2 * 128 * LDA;        // [2][16][72]
    __nv_bfloat16* Wlo = Whi + 2 * 16 * LDW;
    float* stg = (float*)buf;                        // [128][68] epilogue reuse

    const int tid = threadIdx.x;
    const int w = tid >> 5;
    const int wm = w >> 1;
    const int wn = w & 1;
    const int row0 = blockIdx.y * 128;
    const int col0 = blockIdx.x * 64;

    const int ar = tid >> 1, ac = (tid & 1) * 8;     // A: one uint4 (8 bf16)/plane
    const int wr = tid >> 4, wc = (tid & 15) * 4;    // W: one uint2 (4 bf16)/plane

    bfrag_c acc[2][2];
#pragma unroll
    for (int ti = 0; ti < 2; ti++)
#pragma unroll
        for (int tj = 0; tj < 2; tj++) wmma::fill_fragment(acc[ti][tj], 0.0f);

    uint4 pAh, pAl;
    uint2 pWh, pWl;
    pAh = *(const uint4*)&Ah[(size_t)(row0 + ar) * 1024 + ac];
    pAl = *(const uint4*)&Al[(size_t)(row0 + ar) * 1024 + ac];
    pWh = *(const uint2*)&Wh[(size_t)wr * N + col0 + wc];
    pWl = *(const uint2*)&Wl[(size_t)wr * N + col0 + wc];
    *(uint4*)&Ahi[ar * LDA + ac] = pAh;
    *(uint4*)&Alo[ar * LDA + ac] = pAl;
    *(uint2*)&Whi[wr * LDW + wc] = pWh;
    *(uint2*)&Wlo[wr * LDW + wc] = pWl;
    __syncthreads();

    for (int kt = 0; kt < 64; kt++) {
        if (kt < 63) {
            int k = (kt + 1) * 16;
            pAh = *(const uint4*)&Ah[(size_t)(row0 + ar) * 1024 + k + ac];
            pAl = *(const uint4*)&Al[(size_t)(row0 + ar) * 1024 + k + ac];
            pWh = *(const uint2*)&Wh[(size_t)(k + wr) * N + col0 + wc];
            pWl = *(const uint2*)&Wl[(size_t)(k + wr) * N + col0 + wc];
        }
        const int cur = kt & 1;
        const int cb = cur * 128 * LDA;
        const int wb = cur * 16 * LDW;

        bfrag_a fah[2], fal[2];
        bfrag_b fbh[2], fbl[2];
#pragma unroll
        for (int ti = 0; ti < 2; ti++) {
            wmma::load_matrix_sync(fah[ti], Ahi + cb + (wm * 32 + ti * 16) * LDA, LDA);
            wmma::load_matrix_sync(fal[ti], Alo + cb + (wm * 32 + ti * 16) * LDA, LDA);
        }
#pragma unroll
        for (int tj = 0; tj < 2; tj++) {
            wmma::load_matrix_sync(fbh[tj], Whi + wb + wn * 32 + tj * 16, LDW);
            wmma::load_matrix_sync(fbl[tj], Wlo + wb + wn * 32 + tj * 16, LDW);
        }
#pragma unroll
        for (int ti = 0; ti < 2; ti++)
#pragma unroll
            for (int tj = 0; tj < 2; tj++) {
                wmma::mma_sync(acc[ti][tj], fah[ti], fbh[tj], acc[ti][tj]);
                wmma::mma_sync(acc[ti][tj], fah[ti], fbl[tj], acc[ti][tj]);
                wmma::mma_sync(acc[ti][tj], fal[ti], fbh[tj], acc[ti][tj]);
            }

        if (kt < 63) {
            const int nb = (cur ^ 1) * 128 * LDA;
            const int nw = (cur ^ 1) * 16 * LDW;
            *(uint4*)&Ahi[nb + ar * LDA + ac] = pAh;
            *(uint4*)&Alo[nb + ar * LDA + ac] = pAl;
            *(uint2*)&Whi[nw + wr * LDW + wc] = pWh;
            *(uint2*)&Wlo[nw + wr * LDW + wc] = pWl;
        }
        __syncthreads();
    }

#pragma unroll
    for (int ti = 0; ti < 2; ti++)
#pragma unroll
        for (int tj = 0; tj < 2; tj++)
            wmma::store_matrix_sync(&stg[(wm * 32 + ti * 16) * LDST + wn * 32 + tj * 16],
                                    acc[ti][tj], LDST, wmma::mem_row_major);
    __syncthreads();

    float4 bi = *(const float4*)&bias[col0 + ((tid & 15) * 4)];
#pragma unroll
    for (int i = tid; i < 2048; i += 256) {
        int r = i >> 4, c4 = (i & 15) * 4;
        float4 v = *(float4*)&stg[r * LDST + c4];
        v.x += bi.x; v.y += bi.y; v.z += bi.z; v.w += bi.w;
        if (OUTMODE == 0) {
            *(float4*)&Cf[(size_t)(row0 + r) * 1024 + col0 + c4] = v;
        } else {
            int b = (row0 + r) >> 10, s = (row0 + r) & 1023;
            int h = blockIdx.x;
            size_t o = (((size_t)b * Hc + h) * Sc + s) * 64 + c4;
            cvt_store4(Ch + o, Cl + o, v);
        }
    }
}

// ---------------------------------------------------------------------------
// Context GEMM: per z, ctx = attn[z] (fp32, cvt in loop) @ V[z] (planes).
// BM=128, full N=64. Output: ctx hi/lo planes in concat layout.
// ---------------------------------------------------------------------------
__global__ __launch_bounds__(256)
void context_planes(const float* __restrict__ attn,
                    const __nv_bfloat16* __restrict__ Vh, const __nv_bfloat16* __restrict__ Vl,
                    __nv_bfloat16* __restrict__ Ch, __nv_bfloat16* __restrict__ Cl) {
    constexpr int LDA = 24;
    constexpr int LDW = 72;
    constexpr int LDST = 68;

    __shared__ __align__(16) char buf[34816];
    __nv_bfloat16* Ahi = (__nv_bfloat16*)buf;
    __nv_bfloat16* Alo = Ahi + 2 * 128 * LDA;
    __nv_bfloat16* Whi = Alo + 2 * 128 * LDA;
    __nv_bfloat16* Wlo = Whi + 2 * 16 * LDW;
    float* stg = (float*)buf;

    const int tid = threadIdx.x;
    const int w = tid >> 5;
    const int wm = w >> 1;
    const int wn = w & 1;
    const int z = blockIdx.y;
    const int row0 = blockIdx.x * 128;

    const float* Ab = attn + (size_t)z * Sc * Sc;
    const __nv_bfloat16* Vbh = Vh + (size_t)z * Sc * 64;
    const __nv_bfloat16* Vbl = Vl + (size_t)z * Sc * 64;

    const int ar = tid >> 2, ac = (tid & 3) * 4;     // A fp32: 2 float4/thread
    const int wr = tid >> 4, wc = (tid & 15) * 4;    // V: uint2/plane

    bfrag_c acc[2][2];
#pragma unroll
    for (int ti = 0; ti < 2; ti++)
#pragma unroll
        for (int tj = 0; tj < 2; tj++) wmma::fill_fragment(acc[ti][tj], 0.0f);

    float4 ra0, ra1;
    uint2 pWh, pWl;
    ra0 = *(const float4*)&Ab[(size_t)(row0 + ar) * 1024 + ac];
    ra1 = *(const float4*)&Ab[(size_t)(row0 + ar + 64) * 1024 + ac];
    pWh = *(const uint2*)&Vbh[(size_t)wr * 64 + wc];
    pWl = *(const uint2*)&Vbl[(size_t)wr * 64 + wc];
    cvt_store4(Ahi + ar * LDA + ac, Alo + ar * LDA + ac, ra0);
    cvt_store4(Ahi + (ar + 64) * LDA + ac, Alo + (ar + 64) * LDA + ac, ra1);
    *(uint2*)&Whi[wr * LDW + wc] = pWh;
    *(uint2*)&Wlo[wr * LDW + wc] = pWl;
    __syncthreads();

    for (int kt = 0; kt < 64; kt++) {
        if (kt < 63) {
            int k = (kt + 1) * 16;
            ra0 = *(const float4*)&Ab[(size_t)(row0 + ar) * 1024 + k + ac];
            ra1 = *(const float4*)&Ab[(size_t)(row0 + ar + 64) * 1024 + k + ac];
            pWh = *(const uint2*)&Vbh[(size_t)(k + wr) * 64 + wc];
            pWl = *(const uint2*)&Vbl[(size_t)(k + wr) * 64 + wc];
        }
        const int cur = kt & 1;
        const int cb = cur * 128 * LDA;
        const int wb = cur * 16 * LDW;

        bfrag_a fah[2], fal[2];
        bfrag_b fbh[2], fbl[2];
#pragma unroll
        for (int ti = 0; ti < 2; ti++) {
            wmma::load_matrix_sync(fah[ti], Ahi + cb + (wm * 32 + ti * 16) * LDA, LDA);
            wmma::load_matrix_sync(fal[ti], Alo + cb + (wm * 32 + ti * 16) * LDA, LDA);
        }
#pragma unroll
        for (int tj = 0; tj < 2; tj++) {
            wmma::load_matrix_sync(fbh[tj], Whi + wb + wn * 32 + tj * 16, LDW);
            wmma::load_matrix_sync(fbl[tj], Wlo + wb + wn * 32 + tj * 16, LDW);
        }
#pragma unroll
        for (int ti = 0; ti < 2; ti++)
#pragma unroll
            for (int tj = 0; tj < 2; tj++) {
                wmma::mma_sync(acc[ti][tj], fah[ti], fbh[tj], acc[ti][tj]);
                wmma::mma_sync(acc[ti][tj], fah[ti], fbl[tj], acc[ti][tj]);
                wmma::mma_sync(acc[ti][tj], fal[ti], fbh[tj], acc[ti][tj]);
            }

        if (kt < 63) {
            const int nb = (cur ^ 1) * 128 * LDA;
            const int nw = (cur ^ 1) * 16 * LDW;
            cvt_store4(Ahi + nb + ar * LDA + ac, Alo + nb + ar * LDA + ac, ra0);
            cvt_store4(Ahi + nb + (ar + 64) * LDA + ac, Alo + nb + (ar + 64) * LDA + ac, ra1);
            *(uint2*)&Whi[nw + wr * LDW + wc] = pWh;
            *(uint2*)&Wlo[nw + wr * LDW + wc] = pWl;
        }
        __syncthreads();
    }

#pragma unroll
    for (int ti = 0; ti < 2; ti++)
#pragma unroll
        for (int tj = 0; tj < 2; tj++)
            wmma::store_matrix_sync(&stg[(wm * 32 + ti * 16) * LDST + wn * 32 + tj * 16],
                                    acc[ti][tj], LDST, wmma::mem_row_major);
    __syncthreads();

    const int b = z >> 4, h = z & 15;
#pragma unroll
    for (int i = tid; i < 2048; i += 256) {
        int r = i >> 4, c4 = (i & 15) * 4;
        float4 v = *(float4*)&stg[r * LDST + c4];
        size_t o = ((size_t)(b * Sc + row0 + r)) * HDc + h * DVc + c4;
        cvt_store4(Ch + o, Cl + o, v);
    }
}

// ---------------------------------------------------------------------------
// Fused scores + mask + softmax, conversion-free (plane inputs), K double-buf.
// Block: 32 q-rows of one (b,h), full K=1024. Probs written to gmem once.
// ---------------------------------------------------------------------------
#define LDS_F 1032
#define LDT_F 72
#define FUSED_SMEM (32 * LDS_F * 4 + 2 * 32 * LDT_F * 2 + 4 * 64 * LDT_F * 2)

__global__ __launch_bounds__(256)
void fused_scores_softmax(const __nv_bfloat16* __restrict__ Qh, const __nv_bfloat16* __restrict__ Ql,
                          const __nv_bfloat16* __restrict__ Kh, const __nv_bfloat16* __restrict__ Kl,
                          const void* __restrict__ mask, float* __restrict__ attn) {
    extern __shared__ __align__(16) char dbuf[];
    float* Sbuf = (float*)dbuf;                                  // [32][1032]
    __nv_bfloat16* Qhi = (__nv_bfloat16*)(dbuf + 32 * LDS_F * 4);
    __nv_bfloat16* Qlo = Qhi + 32 * LDT_F;
    __nv_bfloat16* Khi = Qlo + 32 * LDT_F;                       // [2][64][72]
    __nv_bfloat16* Klo = Khi + 2 * 64 * LDT_F;

    const int z = blockIdx.y;
    const int b = z >> 4;
    const int q0 = blockIdx.x * 32;
    const int tid = threadIdx.x;
    const int w = tid >> 5;
    const int lane = tid & 31;
    const int wm = w & 1;
    const int wn = w >> 1;

    const __nv_bfloat16* Qbh = Qh + (size_t)z * Sc * 64;
    const __nv_bfloat16* Qbl = Ql + (size_t)z * Sc * 64;
    const __nv_bfloat16* Kbh = Kh + (size_t)z * Sc * 64;
    const __nv_bfloat16* Kbl = Kl + (size_t)z * Sc * 64;

    // Q tile 32x64: 256 uint4 per plane -> 1/thread
    {
        int r = tid >> 3, c = (tid & 7) * 8;
        *(uint4*)&Qhi[r * LDT_F + c] = *(const uint4*)&Qbh[(size_t)(q0 + r) * 64 + c];
        *(uint4*)&Qlo[r * LDT_F + c] = *(const uint4*)&Qbl[(size_t)(q0 + r) * 64 + c];
    }

    // K tiles: 64x64 = 512 uint4/plane -> 2/thread/plane
    const int kr0 = tid >> 3, kc0 = (tid & 7) * 8;
    const int kr1 = (tid + 256) >> 3, kc1 = ((tid + 256) & 7) * 8;

    uint4 ph0, ph1, pl0, pl1;
    ph0 = *(const uint4*)&Kbh[(size_t)kr0 * 64 + kc0];
    ph1 = *(const uint4*)&Kbh[(size_t)kr1 * 64 + kc1];
    pl0 = *(const uint4*)&Kbl[(size_t)kr0 * 64 + kc0];
    pl1 = *(const uint4*)&Kbl[(size_t)kr1 * 64 + kc1];
    *(uint4*)&Khi[kr0 * LDT_F + kc0] = ph0;
    *(uint4*)&Khi[kr1 * LDT_F + kc1] = ph1;
    *(uint4*)&Klo[kr0 * LDT_F + kc0] = pl0;
    *(uint4*)&Klo[kr1 * LDT_F + kc1] = pl1;
    __syncthreads();

    for (int kt = 0; kt < 16; kt++) {
        if (kt < 15) {
            size_t base = (size_t)(kt + 1) * 64 * 64;
            ph0 = *(const uint4*)&Kbh[base + (size_t)kr0 * 64 + kc0];
            ph1 = *(const uint4*)&Kbh[base + (size_t)kr1 * 64 + kc1];
            pl0 = *(const uint4*)&Kbl[base + (size_t)kr0 * 64 + kc0];
            pl1 = *(const uint4*)&Kbl[base + (size_t)kr1 * 64 + kc1];
        }
        const int cur = (kt & 1) * 64 * LDT_F;

        bfrag_c acc;
        wmma::fill_fragment(acc, 0.0f);
#pragma unroll
        for (int ks = 0; ks < 4; ks++) {
            const int kb = ks * 16;
            bfrag_a fah, fal;
            bfrag_bc fbh, fbl;
            wmma::load_matrix_sync(fah, Qhi + (wm * 16) * LDT_F + kb, LDT_F);
            wmma::load_matrix_sync(fal, Qlo + (wm * 16) * LDT_F + kb, LDT_F);
            wmma::load_matrix_sync(fbh, Khi + cur + (wn * 16) * LDT_F + kb, LDT_F);
            wmma::load_matrix_sync(fbl, Klo + cur + (wn * 16) * LDT_F + kb, LDT_F);
            wmma::mma_sync(acc, fah, fbh, acc);
            wmma::mma_sync(acc, fah, fbl, acc);
            wmma::mma_sync(acc, fal, fbh, acc);
        }
        wmma::store_matrix_sync(&Sbuf[(wm * 16) * LDS_F + kt * 64 + wn * 16], acc,
                                LDS_F, wmma::mem_row_major);

        if (kt < 15) {
            const int nxt = ((kt + 1) & 1) * 64 * LDT_F;
            *(uint4*)&Khi[nxt + kr0 * LDT_F + kc0] = ph0;
            *(uint4*)&Khi[nxt + kr1 * LDT_F + kc1] = ph1;
            *(uint4*)&Klo[nxt + kr0 * LDT_F + kc0] = pl0;
            *(uint4*)&Klo[nxt + kr1 * LDT_F + kc1] = pl1;
        }
        __syncthreads();
    }

    // Mask + scale + softmax: warp w owns rows [w*4, w*4+4)
    const int mode = g_mask_mode;
    const int* mi = (const int*)mask;
    const unsigned char* mb8 = (const unsigned char*)mask;
    const float* mf = (const float*)mask;

    for (int rr = 0; rr < 4; rr++) {
        const int r = w * 4 + rr;
        const int q = q0 + r;
        float* Srow = Sbuf + r * LDS_F;
        const size_t mrow = (size_t)b * Sc * Sc + (size_t)q * Sc;

        float mx = -3.0e38f;
#pragma unroll
        for (int i = 0; i < 32; i++) {
            int k = lane + i * 32;
            bool masked;
            if (mode == 0)      masked = (mi[mrow + k] != 0);
            else if (mode == 2) masked = (mf[mrow + k] != 0.0f);
            else                masked = (mb8[mrow + k] != 0);
            float v = masked ? -1e9f : Srow[k] * 0.125f;
            Srow[k] = v;
            mx = fmaxf(mx, v);
        }
#pragma unroll
        for (int o = 16; o; o >>= 1) mx = fmaxf(mx, __shfl_xor_sync(0xffffffffu, mx, o));

        float sum = 0.0f;
#pragma unroll
        for (int i = 0; i < 32; i++) {
            int k = lane + i * 32;
            float e = expf(Srow[k] - mx);
            Srow[k] = e;
            sum += e;
        }
#pragma unroll
        for (int o = 16; o; o >>= 1) sum += __shfl_xor_sync(0xffffffffu, sum, o);
        float inv = 1.0f / sum;

        float4* dst = (float4*)(attn + ((size_t)z * Sc + q) * Sc);
#pragma unroll
        for (int i = 0; i < 8; i++) {
            int k4 = lane + i * 32;
            float4 v = *(float4*)&Srow[k4 * 4];
            v.x *= inv; v.y *= inv; v.z *= inv; v.w *= inv;
            dst[k4] = v;
        }
    }
}

// ---------------------------------------------------------------------------
// Fused residual add + LayerNorm, vectorized.
// ---------------------------------------------------------------------------
__global__ __launch_bounds__(256)
void layernorm_kernel(const float* __restrict__ x, const float* __restrict__ resid,
                      float* __restrict__ out) {
    const size_t row = blockIdx.x;
    const float4* xr = (const float4*)(x + row * Dc);
    const float4* rr = (const float4*)(resid + row * Dc);
    float4* orow = (float4*)(out + row * Dc);
    const int tid = threadIdx.x;
    const int lane = tid & 31, wid = tid >> 5;
    __shared__ float sm[16];

    float4 a = xr[tid], b = rr[tid];
    float4 v = make_float4(a.x + b.x, a.y + b.y, a.z + b.z, a.w + b.w);
    float s = (v.x + v.y) + (v.z + v.w);
#pragma unroll
    for (int o = 16; o; o >>= 1) s += __shfl_xor_sync(0xffffffffu, s, o);
    if (lane == 0) sm[wid] = s;
    __syncthreads();
    float tot = 0.0f;
#pragma unroll
    for (int i = 0; i < 8; i++) tot += sm[i];
    float mean = tot * (1.0f / 1024.0f);

    float dx = v.x - mean, dy = v.y - mean, dz = v.z - mean, dw = v.w - mean;
    float vs = (dx * dx + dy * dy) + (dz * dz + dw * dw);
#pragma unroll
    for (int o = 16; o; o >>= 1) vs += __shfl_xor_sync(0xffffffffu, vs, o);
    if (lane == 0) sm[8 + wid] = vs;
    __syncthreads();
    float vtot = 0.0f;
#pragma unroll
    for (int i = 0; i < 8; i++) vtot += sm[8 + i];
    float inv = rsqrtf(vtot * (1.0f / 1024.0f) + 1e-5f);
    orow[tid] = make_float4(dx * inv, dy * inv, dz * inv, dw * inv);
}

// ---------------------------------------------------------------------------
// Launch
// ---------------------------------------------------------------------------
extern "C" void kernel_launch(void* const* d_in, const int* in_sizes, int n_in,
                              void* d_out, int out_size) {
    const float* q    = (const float*)d_in[0];
    const float* k    = (const float*)d_in[1];
    const float* v    = (const float*)d_in[2];
    const void*  mask = d_in[3];
    const float* Wq   = (const float*)d_in[4];
    const float* bq   = (const float*)d_in[5];
    const float* Wk   = (const float*)d_in[6];
    const float* bk   = (const float*)d_in[7];
    const float* Wv   = (const float*)d_in[8];
    const float* bv   = (const float*)d_in[9];
    const float* Wo   = (const float*)d_in[10];
    const float* bo   = (const float*)d_in[11];
    float* out = (float*)d_out;

    __nv_bfloat16 *qh, *ql, *kh, *kl, *vh, *vl;
    __nv_bfloat16 *Wqh, *Wql, *Wkh, *Wkl, *Wvh, *Wvl, *Woh, *Wol;
    __nv_bfloat16 *Qph, *Qpl, *Kph, *Kpl, *Vph, *Vpl, *ctxh, *ctxl;
    float *obuf, *attn_fb;
    cudaGetSymbolAddress((void**)&qh, g_qh);   cudaGetSymbolAddress((void**)&ql, g_ql);
    cudaGetSymbolAddress((void**)&kh, g_kh);   cudaGetSymbolAddress((void**)&kl, g_kl);
    cudaGetSymbolAddress((void**)&vh, g_vh);   cudaGetSymbolAddress((void**)&vl, g_vl);
    cudaGetSymbolAddress((void**)&Wqh, g_Wqh); cudaGetSymbolAddress((void**)&Wql, g_Wql);
    cudaGetSymbolAddress((void**)&Wkh, g_Wkh); cudaGetSymbolAddress((void**)&Wkl, g_Wkl);
    cudaGetSymbolAddress((void**)&Wvh, g_Wvh); cudaGetSymbolAddress((void**)&Wvl, g_Wvl);
    cudaGetSymbolAddress((void**)&Woh, g_Woh); cudaGetSymbolAddress((void**)&Wol, g_Wol);
    cudaGetSymbolAddress((void**)&Qph, g_Qph); cudaGetSymbolAddress((void**)&Qpl, g_Qpl);
    cudaGetSymbolAddress((void**)&Kph, g_Kph); cudaGetSymbolAddress((void**)&Kpl, g_Kpl);
    cudaGetSymbolAddress((void**)&Vph, g_Vph); cudaGetSymbolAddress((void**)&Vpl, g_Vpl);
    cudaGetSymbolAddress((void**)&ctxh, g_ctxh); cudaGetSymbolAddress((void**)&ctxl, g_ctxl);
    cudaGetSymbolAddress((void**)&obuf, g_obuf);
    cudaGetSymbolAddress((void**)&attn_fb, g_attn_fb);

    const long long LN_ELEMS = (long long)Mc * Dc;
    const long long ATTN_ELEMS = (long long)Bc * Hc * Sc * Sc;
    float* attn = ((long long)out_size >= LN_ELEMS + ATTN_ELEMS)
                      ? (out + (size_t)LN_ELEMS)
                      : attn_fb;

    static int smem_set = 0;
    if (!smem_set) {
        cudaFuncSetAttribute(fused_scores_softmax,
                             cudaFuncAttributeMaxDynamicSharedMemorySize, FUSED_SMEM);
        smem_set = 1;
    }

    detect_mask_kernel<<<1, 1>>>((const unsigned int*)mask);

    // Pre-convert inputs and weights to hi/lo bf16 planes
    cvt_pair_kernel<<<1024, 256>>>((const float4*)q, qh, ql, Mc * Dc / 4);
    cvt_pair_kernel<<<1024, 256>>>((const float4*)k, kh, kl, Mc * Dc / 4);
    cvt_pair_kernel<<<1024, 256>>>((const float4*)v, vh, vl, Mc * Dc / 4);
    cvt_pair_kernel<<<512, 256>>>((const float4*)Wq, Wqh, Wql, Dc * HDc / 4);
    cvt_pair_kernel<<<512, 256>>>((const float4*)Wk, Wkh, Wkl, Dc * HDc / 4);
    cvt_pair_kernel<<<512, 256>>>((const float4*)Wv, Wvh, Wvl, Dc * HDc / 4);
    cvt_pair_kernel<<<512, 256>>>((const float4*)Wo, Woh, Wol, Dc * HDc / 4);

    // Projections (plane in, plane out)
    gemm_planes<1><<<dim3(16, 32), 256>>>(qh, ql, Wqh, Wql, bq, nullptr, Qph, Qpl, HDc);
    gemm_planes<1><<<dim3(16, 32), 256>>>(kh, kl, Wkh, Wkl, bk, nullptr, Kph, Kpl, HDc);
    gemm_planes<1><<<dim3(16, 32), 256>>>(vh, vl, Wvh, Wvl, bv, nullptr, Vph, Vpl, HDc);

    // Fused scores + mask + softmax -> normalized probs
    fused_scores_softmax<<<dim3(32, Bc * Hc), 256, FUSED_SMEM>>>(Qph, Qpl, Kph, Kpl, mask, attn);

    // Context GEMM -> ctx planes (concat layout)
    context_planes<<<dim3(8, 64), 256>>>(attn, Vph, Vpl, ctxh, ctxl);

    // Output projection (plane in, fp32 out)
    gemm_planes<0><<<dim3(16, 32), 256>>>(ctxh, ctxl, Woh, Wol, bo, obuf, nullptr, nullptr, Dc);

    // Residual + LayerNorm
    layernorm_kernel<<<Mc, 256>>>(obuf, q, out);
}

// round 6
// speedup vs baseline: 1.2890x; 1.2890x over previous
#include <cuda_runtime.h>
#include <cuda_bf16.h>
#include <mma.h>
#include <cstddef>

using namespace nvcuda;

// Problem constants
#define Bc 4
#define Sc 1024
#define Dc 1024
#define Hc 16
#define DKc 64
#define DVc 64
#define Mc (Bc * Sc)        // 4096
#define HDc (Hc * DKc)      // 1024
#define QP_ELEMS (Mc * HDc)

// ---------------- Static device scratch ----------------
__device__ __nv_bfloat16 g_Qph[QP_ELEMS], g_Qpl[QP_ELEMS];   // [B,H,S,64] hi/lo
__device__ __nv_bfloat16 g_Kph[QP_ELEMS], g_Kpl[QP_ELEMS];
__device__ __nv_bfloat16 g_Vp[QP_ELEMS];                     // [B,H,S,64] single
__device__ __nv_bfloat16 g_ctx[Mc * HDc];                    // [B,S,1024] single
__device__ float g_obuf[Mc * Dc];
__device__ float g_attn_fb[(size_t)Bc * Hc * Sc * Sc];
__device__ int   g_mask_mode;

// bf16 fragments (16x16x16)
using bfrag_a  = wmma::fragment<wmma::matrix_a, 16, 16, 16, __nv_bfloat16, wmma::row_major>;
using bfrag_b  = wmma::fragment<wmma::matrix_b, 16, 16, 16, __nv_bfloat16, wmma::row_major>;
using bfrag_bc = wmma::fragment<wmma::matrix_b, 16, 16, 16, __nv_bfloat16, wmma::col_major>;
using bfrag_c  = wmma::fragment<wmma::accumulator, 16, 16, 16, float>;

__device__ __forceinline__ void cvt_store4(__nv_bfloat16* dh, __nv_bfloat16* dl, float4 v) {
    float a[4] = {v.x, v.y, v.z, v.w};
#pragma unroll
    for (int j = 0; j < 4; j++) {
        __nv_bfloat16 h = __float2bfloat16(a[j]);
        dh[j] = h;
        dl[j] = __float2bfloat16(a[j] - __bfloat162float(h));
    }
}

__device__ __forceinline__ void cvt_store4_s(__nv_bfloat16* dh, float4 v) {
    dh[0] = __float2bfloat16(v.x);
    dh[1] = __float2bfloat16(v.y);
    dh[2] = __float2bfloat16(v.z);
    dh[3] = __float2bfloat16(v.w);
}

// ---------------------------------------------------------------------------
// Mask dtype detection
// ---------------------------------------------------------------------------
__global__ void detect_mask_kernel(const unsigned int* __restrict__ m) {
    bool allint = true, allfloat = true;
    for (int i = 0; i < 1024; i++) {
        unsigned int w = m[i];
        if (w > 1u) allint = false;
        if (w != 0u && w != 0x3F800000u) allfloat = false;
    }
    g_mask_mode = allint ? 0 : (allfloat ? 2 : 1);
}

// ---------------------------------------------------------------------------
// Split-bf16 projection GEMM (Q/K): fp32 in, cvt in-loop, 3-term split.
// BM=128, BN=64 (one head per block-col), BK=16, double-buffered.
// Epilogue: +bias, write hi/lo bf16 planes to [B,H,S,64].
// ---------------------------------------------------------------------------
__global__ __launch_bounds__(256)
void proj_split(const float* __restrict__ A, const float* __restrict__ W,
                const float* __restrict__ bias,
                __nv_bfloat16* __restrict__ Ch, __nv_bfloat16* __restrict__ Cl) {
    constexpr int LDA = 24;
    constexpr int LDW = 72;
    constexpr int LDST = 68;

    __shared__ __align__(16) char buf[34816];
    __nv_bfloat16* Ahi = (__nv_bfloat16*)buf;
    __nv_bfloat16* Alo = Ahi + 2 * 128 * LDA;
    __nv_bfloat16* Whi = Alo + 2 * 128 * LDA;
    __nv_bfloat16* Wlo = Whi + 2 * 16 * LDW;
    float* stg = (float*)buf;

    const int tid = threadIdx.x;
    const int w = tid >> 5;
    const int wm = w >> 1;
    const int wn = w & 1;
    const int row0 = blockIdx.y * 128;
    const int col0 = blockIdx.x * 64;

    const int ar = tid >> 2, ac = (tid & 3) * 4;
    const int wr = tid >> 4, wc = (tid & 15) * 4;

    bfrag_c acc[2][2];
#pragma unroll
    for (int ti = 0; ti < 2; ti++)
#pragma unroll
        for (int tj = 0; tj < 2; tj++) wmma::fill_fragment(acc[ti][tj], 0.0f);

    float4 ra0, ra1, rw;
    ra0 = *(const float4*)&A[(size_t)(row0 + ar) * Dc + ac];
    ra1 = *(const float4*)&A[(size_t)(row0 + ar + 64) * Dc + ac];
    rw  = *(const float4*)&W[(size_t)wr * HDc + col0 + wc];
    cvt_store4(Ahi + ar * LDA + ac, Alo + ar * LDA + ac, ra0);
    cvt_store4(Ahi + (ar + 64) * LDA + ac, Alo + (ar + 64) * LDA + ac, ra1);
    cvt_store4(Whi + wr * LDW + wc, Wlo + wr * LDW + wc, rw);
    __syncthreads();

    for (int kt = 0; kt < 64; kt++) {
        if (kt < 63) {
            int k = (kt + 1) * 16;
            ra0 = *(const float4*)&A[(size_t)(row0 + ar) * Dc + k + ac];
            ra1 = *(const float4*)&A[(size_t)(row0 + ar + 64) * Dc + k + ac];
            rw  = *(const float4*)&W[(size_t)(k + wr) * HDc + col0 + wc];
        }
        const int cur = kt & 1;
        const int cb = cur * 128 * LDA;
        const int wb = cur * 16 * LDW;

        bfrag_a fah[2], fal[2];
        bfrag_b fbh[2], fbl[2];
#pragma unroll
        for (int ti = 0; ti < 2; ti++) {
            wmma::load_matrix_sync(fah[ti], Ahi + cb + (wm * 32 + ti * 16) * LDA, LDA);
            wmma::load_matrix_sync(fal[ti], Alo + cb + (wm * 32 + ti * 16) * LDA, LDA);
        }
#pragma unroll
        for (int tj = 0; tj < 2; tj++) {
            wmma::load_matrix_sync(fbh[tj], Whi + wb + wn * 32 + tj * 16, LDW);
            wmma::load_matrix_sync(fbl[tj], Wlo + wb + wn * 32 + tj * 16, LDW);
        }
#pragma unroll
        for (int ti = 0; ti < 2; ti++)
#pragma unroll
            for (int tj = 0; tj < 2; tj++) {
                wmma::mma_sync(acc[ti][tj], fah[ti], fbh[tj], acc[ti][tj]);
                wmma::mma_sync(acc[ti][tj], fah[ti], fbl[tj], acc[ti][tj]);
                wmma::mma_sync(acc[ti][tj], fal[ti], fbh[tj], acc[ti][tj]);
            }

        if (kt < 63) {
            const int nb = (cur ^ 1) * 128 * LDA;
            const int nw = (cur ^ 1) * 16 * LDW;
            cvt_store4(Ahi + nb + ar * LDA + ac, Alo + nb + ar * LDA + ac, ra0);
            cvt_store4(Ahi + nb + (ar + 64) * LDA + ac, Alo + nb + (ar + 64) * LDA + ac, ra1);
            cvt_store4(Whi + nw + wr * LDW + wc, Wlo + nw + wr * LDW + wc, rw);
        }
        __syncthreads();
    }

#pragma unroll
    for (int ti = 0; ti < 2; ti++)
#pragma unroll
        for (int tj = 0; tj < 2; tj++)
            wmma::store_matrix_sync(&stg[(wm * 32 + ti * 16) * LDST + wn * 32 + tj * 16],
                                    acc[ti][tj], LDST, wmma::mem_row_major);
    __syncthreads();

    const int b = row0 >> 10;
    const int h = blockIdx.x;
    float4 bi = *(const float4*)&bias[col0 + ((tid & 15) * 4)];
#pragma unroll
    for (int i = tid; i < 2048; i += 256) {
        int r = i >> 4, c4 = (i & 15) * 4;
        int s = (row0 + r) & 1023;
        float4 v = *(float4*)&stg[r * LDST + c4];
        v.x += bi.x; v.y += bi.y; v.z += bi.z; v.w += bi.w;
        size_t o = (((size_t)b * Hc + h) * Sc + s) * 64 + c4;
        cvt_store4(Ch + o, Cl + o, v);
    }
}

// ---------------------------------------------------------------------------
// Single-bf16 projection (V): fp32 in, cvt in-loop single, 1 MMA.
// Epilogue: +bias, write single bf16 plane to [B,H,S,64].
// ---------------------------------------------------------------------------
__global__ __launch_bounds__(256)
void proj_single(const float* __restrict__ A, const float* __restrict__ W,
                 const float* __restrict__ bias, __nv_bfloat16* __restrict__ C) {
    constexpr int LDA = 24;
    constexpr int LDW = 72;
    constexpr int LDST = 68;

    __shared__ __align__(16) char buf[34816];
    __nv_bfloat16* As = (__nv_bfloat16*)buf;         // [2][128][24]
    __nv_bfloat16* Ws = As + 2 * 128 * LDA;          // [2][16][72]
    float* stg = (float*)buf;

    const int tid = threadIdx.x;
    const int w = tid >> 5;
    const int wm = w >> 1;
    const int wn = w & 1;
    const int row0 = blockIdx.y * 128;
    const int col0 = blockIdx.x * 64;

    const int ar = tid >> 2, ac = (tid & 3) * 4;
    const int wr = tid >> 4, wc = (tid & 15) * 4;

    bfrag_c acc[2][2];
#pragma unroll
    for (int ti = 0; ti < 2; ti++)
#pragma unroll
        for (int tj = 0; tj < 2; tj++) wmma::fill_fragment(acc[ti][tj], 0.0f);

    float4 ra0, ra1, rw;
    ra0 = *(const float4*)&A[(size_t)(row0 + ar) * Dc + ac];
    ra1 = *(const float4*)&A[(size_t)(row0 + ar + 64) * Dc + ac];
    rw  = *(const float4*)&W[(size_t)wr * HDc + col0 + wc];
    cvt_store4_s(As + ar * LDA + ac, ra0);
    cvt_store4_s(As + (ar + 64) * LDA + ac, ra1);
    cvt_store4_s(Ws + wr * LDW + wc, rw);
    __syncthreads();

    for (int kt = 0; kt < 64; kt++) {
        if (kt < 63) {
            int k = (kt + 1) * 16;
            ra0 = *(const float4*)&A[(size_t)(row0 + ar) * Dc + k + ac];
            ra1 = *(const float4*)&A[(size_t)(row0 + ar + 64) * Dc + k + ac];
            rw  = *(const float4*)&W[(size_t)(k + wr) * HDc + col0 + wc];
        }
        const int cur = kt & 1;
        const int cb = cur * 128 * LDA;
        const int wb = cur * 16 * LDW;

        bfrag_a fa[2];
        bfrag_b fb[2];
#pragma unroll
        for (int ti = 0; ti < 2; ti++)
            wmma::load_matrix_sync(fa[ti], As + cb + (wm * 32 + ti * 16) * LDA, LDA);
#pragma unroll
        for (int tj = 0; tj < 2; tj++)
            wmma::load_matrix_sync(fb[tj], Ws + wb + wn * 32 + tj * 16, LDW);
#pragma unroll
        for (int ti = 0; ti < 2; ti++)
#pragma unroll
            for (int tj = 0; tj < 2; tj++)
                wmma::mma_sync(acc[ti][tj], fa[ti], fb[tj], acc[ti][tj]);

        if (kt < 63) {
            const int nb = (cur ^ 1) * 128 * LDA;
            const int nw = (cur ^ 1) * 16 * LDW;
            cvt_store4_s(As + nb + ar * LDA + ac, ra0);
            cvt_store4_s(As + nb + (ar + 64) * LDA + ac, ra1);
            cvt_store4_s(Ws + nw + wr * LDW + wc, rw);
        }
        __syncthreads();
    }

#pragma unroll
    for (int ti = 0; ti < 2; ti++)
#pragma unroll
        for (int tj = 0; tj < 2; tj++)
            wmma::store_matrix_sync(&stg[(wm * 32 + ti * 16) * LDST + wn * 32 + tj * 16],
                                    acc[ti][tj], LDST, wmma::mem_row_major);
    __syncthreads();

    const int b = row0 >> 10;
    const int h = blockIdx.x;
    float4 bi = *(const float4*)&bias[col0 + ((tid & 15) * 4)];
#pragma unroll
    for (int i = tid; i < 2048; i += 256) {
        int r = i >> 4, c4 = (i & 15) * 4;
        int s = (row0 + r) & 1023;
        float4 v = *(float4*)&stg[r * LDST + c4];
        v.x += bi.x; v.y += bi.y; v.z += bi.z; v.w += bi.w;
        cvt_store4_s(C + (((size_t)b * Hc + h) * Sc + s) * 64 + c4, v);
    }
}

// ---------------------------------------------------------------------------
// Scores from planes: S[q,k'] = (Q.K)/8, masked -> -1e9. 64x64 tile, no cvt.
// ---------------------------------------------------------------------------
__global__ __launch_bounds__(256)
void scores_planes(const __nv_bfloat16* __restrict__ Qh, const __nv_bfloat16* __restrict__ Ql,
                   const __nv_bfloat16* __restrict__ Kh, const __nv_bfloat16* __restrict__ Kl,
                   const void* __restrict__ mask, float* __restrict__ attn) {
    constexpr int LDT = 72;
    constexpr int LDST = 68;

    __shared__ __align__(16) char buf[36864];
    __nv_bfloat16* Qhi = (__nv_bfloat16*)buf;        // [64][72] each
    __nv_bfloat16* Qlo = Qhi + 64 * LDT;
    __nv_bfloat16* Khi = Qlo + 64 * LDT;
    __nv_bfloat16* Klo = Khi + 64 * LDT;
    float* stg = (float*)buf;                        // [64][68] epilogue reuse

    const int z = blockIdx.z;
    const int b = z >> 4;
    const int q0 = blockIdx.y * 64;
    const int k0 = blockIdx.x * 64;
    const int tid = threadIdx.x;
    const int w = tid >> 5;
    const int wm = w & 1;
    const int wn = w >> 1;

    const size_t zb = (size_t)z * Sc * 64;

    // 64x64 bf16 per plane = 512 uint4; 2/thread/plane
#pragma unroll
    for (int i = tid; i < 512; i += 256) {
        int r = i >> 3, c = (i & 7) * 8;
        *(uint4*)&Qhi[r * LDT + c] = *(const uint4*)&Qh[zb + (size_t)(q0 + r) * 64 + c];
        *(uint4*)&Qlo[r * LDT + c] = *(const uint4*)&Ql[zb + (size_t)(q0 + r) * 64 + c];
        *(uint4*)&Khi[r * LDT + c] = *(const uint4*)&Kh[zb + (size_t)(k0 + r) * 64 + c];
        *(uint4*)&Klo[r * LDT + c] = *(const uint4*)&Kl[zb + (size_t)(k0 + r) * 64 + c];
    }
    __syncthreads();

    bfrag_c acc[2];
    wmma::fill_fragment(acc[0], 0.0f);
    wmma::fill_fragment(acc[1], 0.0f);

#pragma unroll
    for (int ks = 0; ks < 4; ks++) {
        const int kb = ks * 16;
        bfrag_a fah[2], fal[2];
#pragma unroll
        for (int ti = 0; ti < 2; ti++) {
            wmma::load_matrix_sync(fah[ti], Qhi + (wm * 32 + ti * 16) * LDT + kb, LDT);
            wmma::load_matrix_sync(fal[ti], Qlo + (wm * 32 + ti * 16) * LDT + kb, LDT);
        }
        bfrag_bc fbh, fbl;
        wmma::load_matrix_sync(fbh, Khi + (wn * 16) * LDT + kb, LDT);
        wmma::load_matrix_sync(fbl, Klo + (wn * 16) * LDT + kb, LDT);
#pragma unroll
        for (int ti = 0; ti < 2; ti++) {
            wmma::mma_sync(acc[ti], fah[ti], fbh, acc[ti]);
            wmma::mma_sync(acc[ti], fah[ti], fbl, acc[ti]);
            wmma::mma_sync(acc[ti], fal[ti], fbh, acc[ti]);
        }
    }
    __syncthreads();
#pragma unroll
    for (int ti = 0; ti < 2; ti++)
        wmma::store_matrix_sync(&stg[(wm * 32 + ti * 16) * LDST + wn * 16], acc[ti],
                                LDST, wmma::mem_row_major);
    __syncthreads();

    const int mode = g_mask_mode;
    const int* mi = (const int*)mask;
    const unsigned char* mb8 = (const unsigned char*)mask;
    const float* mf = (const float*)mask;

#pragma unroll
    for (int i = tid; i < 4096; i += 256) {
        int r = i >> 6, c = i & 63;
        int qq = q0 + r, kk = k0 + c;
        size_t midx = (size_t)b * Sc * Sc + (size_t)qq * Sc + kk;
        bool masked;
        if (mode == 0)      masked = (mi[midx] != 0);
        else if (mode == 2) masked = (mf[midx] != 0.0f);
        else                masked = (mb8[midx] != 0);
        float v = masked ? -1e9f : stg[r * LDST + c] * 0.125f;
        attn[((size_t)z * Sc + qq) * Sc + kk] = v;
    }
}

// ---------------------------------------------------------------------------
// Row softmax (length 1024), in place, vectorized + warp shuffles.
// ---------------------------------------------------------------------------
__global__ __launch_bounds__(256)
void softmax_kernel(float* __restrict__ attn) {
    const size_t row = blockIdx.x;
    float4* p = (float4*)(attn + row * Sc);
    const int tid = threadIdx.x;
    const int lane = tid & 31, wid = tid >> 5;
    __shared__ float sm[16];

    float4 v = p[tid];
    float mx = fmaxf(fmaxf(v.x, v.y), fmaxf(v.z, v.w));
#pragma unroll
    for (int o = 16; o; o >>= 1) mx = fmaxf(mx, __shfl_xor_sync(0xffffffffu, mx, o));
    if (lane == 0) sm[wid] = mx;
    __syncthreads();
    float m = sm[0];
#pragma unroll
    for (int i = 1; i < 8; i++) m = fmaxf(m, sm[i]);

    v.x = expf(v.x - m); v.y = expf(v.y - m);
    v.z = expf(v.z - m); v.w = expf(v.w - m);
    float s = (v.x + v.y) + (v.z + v.w);
#pragma unroll
    for (int o = 16; o; o >>= 1) s += __shfl_xor_sync(0xffffffffu, s, o);
    if (lane == 0) sm[8 + wid] = s;
    __syncthreads();
    float tot = 0.0f;
#pragma unroll
    for (int i = 0; i < 8; i++) tot += sm[8 + i];
    float inv = 1.0f / tot;
    v.x *= inv; v.y *= inv; v.z *= inv; v.w *= inv;
    p[tid] = v;
}

// ---------------------------------------------------------------------------
// Context (single-bf16): per z, ctx = attn[z] @ V[z]; out -> bf16 concat plane.
// ---------------------------------------------------------------------------
__global__ __launch_bounds__(256)
void context_single(const float* __restrict__ attn, const __nv_bfloat16* __restrict__ Vp,
                    __nv_bfloat16* __restrict__ C) {
    constexpr int LDA = 24;
    constexpr int LDW = 72;
    constexpr int LDST = 68;

    __shared__ __align__(16) char buf[34816];
    __nv_bfloat16* As = (__nv_bfloat16*)buf;
    __nv_bfloat16* Ws = As + 2 * 128 * LDA;
    float* stg = (float*)buf;

    const int tid = threadIdx.x;
    const int w = tid >> 5;
    const int wm = w >> 1;
    const int wn = w & 1;
    const int z = blockIdx.y;
    const int row0 = blockIdx.x * 128;

    const float* Ab = attn + (size_t)z * Sc * Sc;
    const __nv_bfloat16* Vb = Vp + (size_t)z * Sc * 64;

    const int ar = tid >> 2, ac = (tid & 3) * 4;
    const int wr = tid >> 4, wc = (tid & 15) * 4;

    bfrag_c acc[2][2];
#pragma unroll
    for (int ti = 0; ti < 2; ti++)
#pragma unroll
        for (int tj = 0; tj < 2; tj++) wmma::fill_fragment(acc[ti][tj], 0.0f);

    float4 ra0, ra1;
    uint2 rv;
    ra0 = *(const float4*)&Ab[(size_t)(row0 + ar) * Sc + ac];
    ra1 = *(const float4*)&Ab[(size_t)(row0 + ar + 64) * Sc + ac];
    rv  = *(const uint2*)&Vb[(size_t)wr * 64 + wc];
    cvt_store4_s(As + ar * LDA + ac, ra0);
    cvt_store4_s(As + (ar + 64) * LDA + ac, ra1);
    *(uint2*)&Ws[wr * LDW + wc] = rv;
    __syncthreads();

    for (int kt = 0; kt < 64; kt++) {
        if (kt < 63) {
            int k = (kt + 1) * 16;
            ra0 = *(const float4*)&Ab[(size_t)(row0 + ar) * Sc + k + ac];
            ra1 = *(const float4*)&Ab[(size_t)(row0 + ar + 64) * Sc + k + ac];
            rv  = *(const uint2*)&Vb[(size_t)(k + wr) * 64 + wc];
        }
        const int cur = kt & 1;
        const int cb = cur * 128 * LDA;
        const int wb = cur * 16 * LDW;

        bfrag_a fa[2];
        bfrag_b fb[2];
#pragma unroll
        for (int ti = 0; ti < 2; ti++)
            wmma::load_matrix_sync(fa[ti], As + cb + (wm * 32 + ti * 16) * LDA, LDA);
#pragma unroll
        for (int tj = 0; tj < 2; tj++)
            wmma::load_matrix_sync(fb[tj], Ws + wb + wn * 32 + tj * 16, LDW);
#pragma unroll
        for (int ti = 0; ti < 2; ti++)
#pragma unroll
            for (int tj = 0; tj < 2; tj++)
                wmma::mma_sync(acc[ti][tj], fa[ti], fb[tj], acc[ti][tj]);

        if (kt < 63) {
            const int nb = (cur ^ 1) * 128 * LDA;
            const int nw = (cur ^ 1) * 16 * LDW;
            cvt_store4_s(As + nb + ar * LDA + ac, ra0);
            cvt_store4_s(As + nb + (ar + 64) * LDA + ac, ra1);
            *(uint2*)&Ws[nw + wr * LDW + wc] = rv;
        }
        __syncthreads();
    }

#pragma unroll
    for (int ti = 0; ti < 2; ti++)
#pragma unroll
        for (int tj = 0; tj < 2; tj++)
            wmma::store_matrix_sync(&stg[(wm * 32 + ti * 16) * LDST + wn * 32 + tj * 16],
                                    acc[ti][tj], LDST, wmma::mem_row_major);
    __syncthreads();

    const int b = z >> 4, h = z & 15;
#pragma unroll
    for (int i = tid; i < 2048; i += 256) {
        int r = i >> 4, c4 = (i & 15) * 4;
        float4 v = *(float4*)&stg[r * LDST + c4];
        cvt_store4_s(C + ((size_t)(b * Sc + row0 + r)) * HDc + h * DVc + c4, v);
    }
}

// ---------------------------------------------------------------------------
// Out-proj (single-bf16): A = ctx bf16 plane, W = Wo fp32 (cvt in-loop).
// ---------------------------------------------------------------------------
__global__ __launch_bounds__(256)
void outproj_single(const __nv_bfloat16* __restrict__ A, const float* __restrict__ W,
                    const float* __restrict__ bias, float* __restrict__ C) {
    constexpr int LDA = 24;
    constexpr int LDW = 72;
    constexpr int LDST = 68;

    __shared__ __align__(16) char buf[34816];
    __nv_bfloat16* As = (__nv_bfloat16*)buf;
    __nv_bfloat16* Ws = As + 2 * 128 * LDA;
    float* stg = (float*)buf;

    const int tid = threadIdx.x;
    const int w = tid >> 5;
    const int wm = w >> 1;
    const int wn = w & 1;
    const int row0 = blockIdx.y * 128;
    const int col0 = blockIdx.x * 64;

    const int ar = tid >> 1, ac = (tid & 1) * 8;     // A: 1 uint4 (8 bf16)/thread
    const int wr = tid >> 4, wc = (tid & 15) * 4;

    bfrag_c acc[2][2];
#pragma unroll
    for (int ti = 0; ti < 2; ti++)
#pragma unroll
        for (int tj = 0; tj < 2; tj++) wmma::fill_fragment(acc[ti][tj], 0.0f);

    uint4 pa;
    float4 rw;
    pa = *(const uint4*)&A[(size_t)(row0 + ar) * 1024 + ac];
    rw = *(const float4*)&W[(size_t)wr * Dc + col0 + wc];
    *(uint4*)&As[ar * LDA + ac] = pa;
    cvt_store4_s(Ws + wr * LDW + wc, rw);
    __syncthreads();

    for (int kt = 0; kt < 64; kt++) {
        if (kt < 63) {
            int k = (kt + 1) * 16;
            pa = *(const uint4*)&A[(size_t)(row0 + ar) * 1024 + k + ac];
            rw = *(const float4*)&W[(size_t)(k + wr) * Dc + col0 + wc];
        }
        const int cur = kt & 1;
        const int cb = cur * 128 * LDA;
        const int wb = cur * 16 * LDW;

        bfrag_a fa[2];
        bfrag_b fb[2];
#pragma unroll
        for (int ti = 0; ti < 2; ti++)
            wmma::load_matrix_sync(fa[ti], As + cb + (wm * 32 + ti * 16) * LDA, LDA);
#pragma unroll
        for (int tj = 0; tj < 2; tj++)
            wmma::load_matrix_sync(fb[tj], Ws + wb + wn * 32 + tj * 16, LDW);
#pragma unroll
        for (int ti = 0; ti < 2; ti++)
#pragma unroll
            for (int tj = 0; tj < 2; tj++)
                wmma::mma_sync(acc[ti][tj], fa[ti], fb[tj], acc[ti][tj]);

        if (kt < 63) {
            const int nb = (cur ^ 1) * 128 * LDA;
            const int nw = (cur ^ 1) * 16 * LDW;
            *(uint4*)&As[nb + ar * LDA + ac] = pa;
            cvt_store4_s(Ws + nw + wr * LDW + wc, rw);
        }
        __syncthreads();
    }

#pragma unroll
    for (int ti = 0; ti < 2; ti++)
#pragma unroll
        for (int tj = 0; tj < 2; tj++)
            wmma::store_matrix_sync(&stg[(wm * 32 + ti * 16) * LDST + wn * 32 + tj * 16],
                                    acc[ti][tj], LDST, wmma::mem_row_major);
    __syncthreads();

    float4 bi = *(const float4*)&bias[col0 + ((tid & 15) * 4)];
#pragma unroll
    for (int i = tid; i < 2048; i += 256) {
        int r = i >> 4, c4 = (i & 15) * 4;
        float4 v = *(float4*)&stg[r * LDST + c4];
        v.x += bi.x; v.y += bi.y; v.z += bi.z; v.w += bi.w;
        *(float4*)&C[(size_t)(row0 + r) * Dc + col0 + c4] = v;
    }
}

// ---------------------------------------------------------------------------
// Fused residual add + LayerNorm, vectorized.
// ---------------------------------------------------------------------------
__global__ __launch_bounds__(256)
void layernorm_kernel(const float* __restrict__ x, const float* __restrict__ resid,
                      float* __restrict__ out) {
    const size_t row = blockIdx.x;
    const float4* xr = (const float4*)(x + row * Dc);
    const float4* rr = (const float4*)(resid + row * Dc);
    float4* orow = (float4*)(out + row * Dc);
    const int tid = threadIdx.x;
    const int lane = tid & 31, wid = tid >> 5;
    __shared__ float sm[16];

    float4 a = xr[tid], b = rr[tid];
    float4 v = make_float4(a.x + b.x, a.y + b.y, a.z + b.z, a.w + b.w);
    float s = (v.x + v.y) + (v.z + v.w);
#pragma unroll
    for (int o = 16; o; o >>= 1) s += __shfl_xor_sync(0xffffffffu, s, o);
    if (lane == 0) sm[wid] = s;
    __syncthreads();
    float tot = 0.0f;
#pragma unroll
    for (int i = 0; i < 8; i++) tot += sm[i];
    float mean = tot * (1.0f / 1024.0f);

    float dx = v.x - mean, dy = v.y - mean, dz = v.z - mean, dw = v.w - mean;
    float vs = (dx * dx + dy * dy) + (dz * dz + dw * dw);
#pragma unroll
    for (int o = 16; o; o >>= 1) vs += __shfl_xor_sync(0xffffffffu, vs, o);
    if (lane == 0) sm[8 + wid] = vs;
    __syncthreads();
    float vtot = 0.0f;
#pragma unroll
    for (int i = 0; i < 8; i++) vtot += sm[8 + i];
    float inv = rsqrtf(vtot * (1.0f / 1024.0f) + 1e-5f);
    orow[tid] = make_float4(dx * inv, dy * inv, dz * inv, dw * inv);
}

// ---------------------------------------------------------------------------
// Launch
// ---------------------------------------------------------------------------
extern "C" void kernel_launch(void* const* d_in, const int* in_sizes, int n_in,
                              void* d_out, int out_size) {
    const float* q    = (const float*)d_in[0];
    const float* k    = (const float*)d_in[1];
    const float* v    = (const float*)d_in[2];
    const void*  mask = d_in[3];
    const float* Wq   = (const float*)d_in[4];
    const float* bq   = (const float*)d_in[5];
    const float* Wk   = (const float*)d_in[6];
    const float* bk   = (const float*)d_in[7];
    const float* Wv   = (const float*)d_in[8];
    const float* bv   = (const float*)d_in[9];
    const float* Wo   = (const float*)d_in[10];
    const float* bo   = (const float*)d_in[11];
    float* out = (float*)d_out;

    __nv_bfloat16 *Qph, *Qpl, *Kph, *Kpl, *Vp, *ctx;
    float *obuf, *attn_fb;
    cudaGetSymbolAddress((void**)&Qph, g_Qph); cudaGetSymbolAddress((void**)&Qpl, g_Qpl);
    cudaGetSymbolAddress((void**)&Kph, g_Kph); cudaGetSymbolAddress((void**)&Kpl, g_Kpl);
    cudaGetSymbolAddress((void**)&Vp, g_Vp);
    cudaGetSymbolAddress((void**)&ctx, g_ctx);
    cudaGetSymbolAddress((void**)&obuf, g_obuf);
    cudaGetSymbolAddress((void**)&attn_fb, g_attn_fb);

    const long long LN_ELEMS = (long long)Mc * Dc;
    const long long ATTN_ELEMS = (long long)Bc * Hc * Sc * Sc;
    float* attn = ((long long)out_size >= LN_ELEMS + ATTN_ELEMS)
                      ? (out + (size_t)LN_ELEMS)
                      : attn_fb;

    detect_mask_kernel<<<1, 1>>>((const unsigned int*)mask);

    // Q/K projections: split-bf16, epilogue writes hi/lo planes
    proj_split<<<dim3(16, 32), 256>>>(q, Wq, bq, Qph, Qpl);
    proj_split<<<dim3(16, 32), 256>>>(k, Wk, bk, Kph, Kpl);
    // V projection: single-bf16
    proj_single<<<dim3(16, 32), 256>>>(v, Wv, bv, Vp);

    // Scores from planes (no in-loop cvt) + mask
    scores_planes<<<dim3(16, 16, Bc * Hc), 256>>>(Qph, Qpl, Kph, Kpl, mask, attn);

    // Softmax in place
    softmax_kernel<<<Bc * Hc * Sc, 256>>>(attn);

    // Context (single-bf16) -> ctx bf16 plane, concat layout
    context_single<<<dim3(8, 64), 256>>>(attn, Vp, ctx);

    // Output projection (single-bf16)
    outproj_single<<<dim3(16, 32), 256>>>(ctx, Wo, bo, obuf);

    // Residual + LayerNorm
    layernorm_kernel<<<Mc, 256>>>(obuf, q, out);
}

// round 7
// speedup vs baseline: 1.5112x; 1.1724x over previous
#include <cuda_runtime.h>
#include <cuda_bf16.h>
#include <mma.h>
#include <cstddef>

using namespace nvcuda;

#define Bc 4
#define Sc 1024
#define Dc 1024
#define Hc 16
#define DKc 64
#define DVc 64
#define Mc (Bc * Sc)
#define HDc (Hc * DKc)
#define QP_ELEMS (Mc * HDc)

// ---------------- Static device scratch ----------------
__device__ __nv_bfloat16 g_Qph[QP_ELEMS], g_Qpl[QP_ELEMS];   // [B,H,S,64] hi/lo
__device__ __nv_bfloat16 g_Kph[QP_ELEMS], g_Kpl[QP_ELEMS];
__device__ __nv_bfloat16 g_Vp[QP_ELEMS];                     // [B,H,S,64]
__device__ __nv_bfloat16 g_ctx[Mc * HDc];                    // [B,S,1024]
__device__ __nv_bfloat16 g_attn_bf[(size_t)Bc * Hc * Sc * Sc]; // bf16 probs
__device__ float g_obuf[Mc * Dc];
__device__ float g_attn_fb[(size_t)Bc * Hc * Sc * Sc];
__device__ int   g_mask_mode;

using bfrag_a  = wmma::fragment<wmma::matrix_a, 16, 16, 16, __nv_bfloat16, wmma::row_major>;
using bfrag_b  = wmma::fragment<wmma::matrix_b, 16, 16, 16, __nv_bfloat16, wmma::row_major>;
using bfrag_bc = wmma::fragment<wmma::matrix_b, 16, 16, 16, __nv_bfloat16, wmma::col_major>;
using bfrag_c  = wmma::fragment<wmma::accumulator, 16, 16, 16, float>;

__device__ __forceinline__ void cvt_store4(__nv_bfloat16* dh, __nv_bfloat16* dl, float4 v) {
    float a[4] = {v.x, v.y, v.z, v.w};
#pragma unroll
    for (int j = 0; j < 4; j++) {
        __nv_bfloat16 h = __float2bfloat16(a[j]);
        dh[j] = h;
        dl[j] = __float2bfloat16(a[j] - __bfloat162float(h));
    }
}

__device__ __forceinline__ void cvt_store4_s(__nv_bfloat16* dh, float4 v) {
    dh[0] = __float2bfloat16(v.x);
    dh[1] = __float2bfloat16(v.y);
    dh[2] = __float2bfloat16(v.z);
    dh[3] = __float2bfloat16(v.w);
}

// ---------------------------------------------------------------------------
__global__ void detect_mask_kernel(const unsigned int* __restrict__ m) {
    bool allint = true, allfloat = true;
    for (int i = 0; i < 1024; i++) {
        unsigned int w = m[i];
        if (w > 1u) allint = false;
        if (w != 0u && w != 0x3F800000u) allfloat = false;
    }
    g_mask_mode = allint ? 0 : (allfloat ? 2 : 1);
}

// ---------------------------------------------------------------------------
// Split-bf16 Q/K projection: BM=128, BN=128, BK=16, warp tile 32x64 (2x4).
// fp32 A,W in (cvt in-loop), epilogue +bias -> hi/lo planes [B,H,S,64].
// ---------------------------------------------------------------------------
__global__ __launch_bounds__(256)
void proj_split_wide(const float* __restrict__ A, const float* __restrict__ W,
                     const float* __restrict__ bias,
                     __nv_bfloat16* __restrict__ Ch, __nv_bfloat16* __restrict__ Cl) {
    constexpr int LDA = 24;    // bf16 ld for BK=16
    constexpr int LDW = 136;   // bf16 ld for BN=128
    constexpr int LDST = 132;  // fp32 staging ld

    __shared__ __align__(16) char buf[41984];
    __nv_bfloat16* Ahi = (__nv_bfloat16*)buf;        // [2][128][24]
    __nv_bfloat16* Alo = Ahi + 2 * 128 * LDA;
    __nv_bfloat16* Whi = Alo + 2 * 128 * LDA;        // [2][16][136]
    __nv_bfloat16* Wlo = Whi + 2 * 16 * LDW;
    float* stg = (float*)buf;                        // [64][132] (phase reuse)

    const int tid = threadIdx.x;
    const int w = tid >> 5;
    const int wm = w >> 1;      // 0..3
    const int wn = w & 1;       // 0..1
    const int row0 = blockIdx.y * 128;
    const int col0 = blockIdx.x * 128;

    const int ar = tid >> 2, ac = (tid & 3) * 4;
    const int wr0 = tid >> 5, wc0 = (tid & 31) * 4;  // W: 2 float4/thread

    bfrag_c acc[2][4];
#pragma unroll
    for (int ti = 0; ti < 2; ti++)
#pragma unroll
        for (int tj = 0; tj < 4; tj++) wmma::fill_fragment(acc[ti][tj], 0.0f);

    float4 ra0, ra1, rw0, rw1;
    ra0 = *(const float4*)&A[(size_t)(row0 + ar) * Dc + ac];
    ra1 = *(const float4*)&A[(size_t)(row0 + ar + 64) * Dc + ac];
    rw0 = *(const float4*)&W[(size_t)wr0 * HDc + col0 + wc0];
    rw1 = *(const float4*)&W[(size_t)(wr0 + 8) * HDc + col0 + wc0];
    cvt_store4(Ahi + ar * LDA + ac, Alo + ar * LDA + ac, ra0);
    cvt_store4(Ahi + (ar + 64) * LDA + ac, Alo + (ar + 64) * LDA + ac, ra1);
    cvt_store4(Whi + wr0 * LDW + wc0, Wlo + wr0 * LDW + wc0, rw0);
    cvt_store4(Whi + (wr0 + 8) * LDW + wc0, Wlo + (wr0 + 8) * LDW + wc0, rw1);
    __syncthreads();

    for (int kt = 0; kt < 64; kt++) {
        if (kt < 63) {
            int k = (kt + 1) * 16;
            ra0 = *(const float4*)&A[(size_t)(row0 + ar) * Dc + k + ac];
            ra1 = *(const float4*)&A[(size_t)(row0 + ar + 64) * Dc + k + ac];
            rw0 = *(const float4*)&W[(size_t)(k + wr0) * HDc + col0 + wc0];
            rw1 = *(const float4*)&W[(size_t)(k + wr0 + 8) * HDc + col0 + wc0];
        }
        const int cur = kt & 1;
        const int cb = cur * 128 * LDA;
        const int wb = cur * 16 * LDW;

        bfrag_a fah[2], fal[2];
#pragma unroll
        for (int ti = 0; ti < 2; ti++) {
            wmma::load_matrix_sync(fah[ti], Ahi + cb + (wm * 32 + ti * 16) * LDA, LDA);
            wmma::load_matrix_sync(fal[ti], Alo + cb + (wm * 32 + ti * 16) * LDA, LDA);
        }
#pragma unroll
        for (int tj = 0; tj < 4; tj++) {
            bfrag_b fbh, fbl;
            wmma::load_matrix_sync(fbh, Whi + wb + wn * 64 + tj * 16, LDW);
            wmma::load_matrix_sync(fbl, Wlo + wb + wn * 64 + tj * 16, LDW);
#pragma unroll
            for (int ti = 0; ti < 2; ti++) {
                wmma::mma_sync(acc[ti][tj], fah[ti], fbh, acc[ti][tj]);
                wmma::mma_sync(acc[ti][tj], fah[ti], fbl, acc[ti][tj]);
                wmma::mma_sync(acc[ti][tj], fal[ti], fbh, acc[ti][tj]);
            }
        }

        if (kt < 63) {
            const int nb = (cur ^ 1) * 128 * LDA;
            const int nw = (cur ^ 1) * 16 * LDW;
            cvt_store4(Ahi + nb + ar * LDA + ac, Alo + nb + ar * LDA + ac, ra0);
            cvt_store4(Ahi + nb + (ar + 64) * LDA + ac, Alo + nb + (ar + 64) * LDA + ac, ra1);
            cvt_store4(Whi + nw + wr0 * LDW + wc0, Wlo + nw + wr0 * LDW + wc0, rw0);
            cvt_store4(Whi + nw + (wr0 + 8) * LDW + wc0, Wlo + nw + (wr0 + 8) * LDW + wc0, rw1);
        }
        __syncthreads();
    }

    // Two-phase epilogue (rows 0-63, then 64-127)
#pragma unroll
    for (int ph = 0; ph < 2; ph++) {
        if ((wm >> 1) == ph) {
#pragma unroll
            for (int ti = 0; ti < 2; ti++)
#pragma unroll
                for (int tj = 0; tj < 4; tj++)
                    wmma::store_matrix_sync(&stg[((wm & 1) * 32 + ti * 16) * LDST + wn * 64 + tj * 16],
                                            acc[ti][tj], LDST, wmma::mem_row_major);
        }
        __syncthreads();
#pragma unroll
        for (int i = tid; i < 2048; i += 256) {
            int r = i >> 5, c4 = (i & 31) * 4;
            int m = row0 + ph * 64 + r;
            int col = col0 + c4;
            float4 v = *(float4*)&stg[r * LDST + c4];
            float4 bi = *(const float4*)&bias[col];
            v.x += bi.x; v.y += bi.y; v.z += bi.z; v.w += bi.w;
            int b = m >> 10, s = m & 1023, h = col >> 6, d = col & 63;
            size_t o = (((size_t)b * Hc + h) * Sc + s) * 64 + d;
            cvt_store4(Ch + o, Cl + o, v);
        }
        __syncthreads();
    }
}

// ---------------------------------------------------------------------------
// Single-bf16 wide GEMM: BM=128, BN=128, warp tile 32x64.
// AFP32=1: A fp32 (cvt in-loop);  AFP32=0: A bf16 plane (raw loads).
// TOOUT=1: +bias -> bf16 plane [B,H,S,64];  TOOUT=0: +bias -> fp32 [*,1024].
// ---------------------------------------------------------------------------
template <int AFP32, int TOOUT>
__global__ __launch_bounds__(256)
void gemm_single_wide(const void* __restrict__ Aptr, const float* __restrict__ W,
                      const float* __restrict__ bias, float* __restrict__ Cf,
                      __nv_bfloat16* __restrict__ Cbf) {
    constexpr int LDA = 24;
    constexpr int LDW = 136;
    constexpr int LDST = 132;

    __shared__ __align__(16) char buf[33792];
    __nv_bfloat16* As = (__nv_bfloat16*)buf;         // [2][128][24]
    __nv_bfloat16* Ws = As + 2 * 128 * LDA;          // [2][16][136]
    float* stg = (float*)buf;                        // [64][132]

    const int tid = threadIdx.x;
    const int w = tid >> 5;
    const int wm = w >> 1;
    const int wn = w & 1;
    const int row0 = blockIdx.y * 128;
    const int col0 = blockIdx.x * 128;

    const float* Af = (const float*)Aptr;
    const __nv_bfloat16* Ab = (const __nv_bfloat16*)Aptr;

    const int ar = tid >> 2, ac = (tid & 3) * 4;     // AFP32 path
    const int br = tid >> 1, bc = (tid & 1) * 8;     // bf16 A path
    const int wr0 = tid >> 5, wc0 = (tid & 31) * 4;

    bfrag_c acc[2][4];
#pragma unroll
    for (int ti = 0; ti < 2; ti++)
#pragma unroll
        for (int tj = 0; tj < 4; tj++) wmma::fill_fragment(acc[ti][tj], 0.0f);

    float4 ra0, ra1, rw0, rw1;
    uint4 pa;
    if (AFP32) {
        ra0 = *(const float4*)&Af[(size_t)(row0 + ar) * Dc + ac];
        ra1 = *(const float4*)&Af[(size_t)(row0 + ar + 64) * Dc + ac];
        cvt_store4_s(As + ar * LDA + ac, ra0);
        cvt_store4_s(As + (ar + 64) * LDA + ac, ra1);
    } else {
        pa = *(const uint4*)&Ab[(size_t)(row0 + br) * Dc + bc];
        *(uint4*)&As[br * LDA + bc] = pa;
    }
    rw0 = *(const float4*)&W[(size_t)wr0 * Dc + col0 + wc0];
    rw1 = *(const float4*)&W[(size_t)(wr0 + 8) * Dc + col0 + wc0];
    cvt_store4_s(Ws + wr0 * LDW + wc0, rw0);
    cvt_store4_s(Ws + (wr0 + 8) * LDW + wc0, rw1);
    __syncthreads();

    for (int kt = 0; kt < 64; kt++) {
        if (kt < 63) {
            int k = (kt + 1) * 16;
            if (AFP32) {
                ra0 = *(const float4*)&Af[(size_t)(row0 + ar) * Dc + k + ac];
                ra1 = *(const float4*)&Af[(size_t)(row0 + ar + 64) * Dc + k + ac];
            } else {
                pa = *(const uint4*)&Ab[(size_t)(row0 + br) * Dc + k + bc];
            }
            rw0 = *(const float4*)&W[(size_t)(k + wr0) * Dc + col0 + wc0];
            rw1 = *(const float4*)&W[(size_t)(k + wr0 + 8) * Dc + col0 + wc0];
        }
        const int cur = kt & 1;
        const int cb = cur * 128 * LDA;
        const int wb = cur * 16 * LDW;

        bfrag_a fa[2];
#pragma unroll
        for (int ti = 0; ti < 2; ti++)
            wmma::load_matrix_sync(fa[ti], As + cb + (wm * 32 + ti * 16) * LDA, LDA);
#pragma unroll
        for (int tj = 0; tj < 4; tj++) {
            bfrag_b fb;
            wmma::load_matrix_sync(fb, Ws + wb + wn * 64 + tj * 16, LDW);
#pragma unroll
            for (int ti = 0; ti < 2; ti++)
                wmma::mma_sync(acc[ti][tj], fa[ti], fb, acc[ti][tj]);
        }

        if (kt < 63) {
            const int nb = (cur ^ 1) * 128 * LDA;
            const int nw = (cur ^ 1) * 16 * LDW;
            if (AFP32) {
                cvt_store4_s(As + nb + ar * LDA + ac, ra0);
                cvt_store4_s(As + nb + (ar + 64) * LDA + ac, ra1);
            } else {
                *(uint4*)&As[nb + br * LDA + bc] = pa;
            }
            cvt_store4_s(Ws + nw + wr0 * LDW + wc0, rw0);
            cvt_store4_s(Ws + nw + (wr0 + 8) * LDW + wc0, rw1);
        }
        __syncthreads();
    }

#pragma unroll
    for (int ph = 0; ph < 2; ph++) {
        if ((wm >> 1) == ph) {
#pragma unroll
            for (int ti = 0; ti < 2; ti++)
#pragma unroll
                for (int tj = 0; tj < 4; tj++)
                    wmma::store_matrix_sync(&stg[((wm & 1) * 32 + ti * 16) * LDST + wn * 64 + tj * 16],
                                            acc[ti][tj], LDST, wmma::mem_row_major);
        }
        __syncthreads();
#pragma unroll
        for (int i = tid; i < 2048; i += 256) {
            int r = i >> 5, c4 = (i & 31) * 4;
            int m = row0 + ph * 64 + r;
            int col = col0 + c4;
            float4 v = *(float4*)&stg[r * LDST + c4];
            float4 bi = *(const float4*)&bias[col];
            v.x += bi.x; v.y += bi.y; v.z += bi.z; v.w += bi.w;
            if (TOOUT == 0) {
                *(float4*)&Cf[(size_t)m * Dc + col] = v;
            } else {
                int b = m >> 10, s = m & 1023, h = col >> 6, d = col & 63;
                cvt_store4_s(Cbf + (((size_t)b * Hc + h) * Sc + s) * 64 + d, v);
            }
        }
        __syncthreads();
    }
}

// ---------------------------------------------------------------------------
// Scores from planes: 64x64 tile per block, split-bf16, mask -> raw scores.
// ---------------------------------------------------------------------------
__global__ __launch_bounds__(256)
void scores_planes(const __nv_bfloat16* __restrict__ Qh, const __nv_bfloat16* __restrict__ Ql,
                   const __nv_bfloat16* __restrict__ Kh, const __nv_bfloat16* __restrict__ Kl,
                   const void* __restrict__ mask, float* __restrict__ attn) {
    constexpr int LDT = 72;
    constexpr int LDST = 68;

    __shared__ __align__(16) char buf[36864];
    __nv_bfloat16* Qhi = (__nv_bfloat16*)buf;
    __nv_bfloat16* Qlo = Qhi + 64 * LDT;
    __nv_bfloat16* Khi = Qlo + 64 * LDT;
    __nv_bfloat16* Klo = Khi + 64 * LDT;
    float* stg = (float*)buf;

    const int z = blockIdx.z;
    const int b = z >> 4;
    const int q0 = blockIdx.y * 64;
    const int k0 = blockIdx.x * 64;
    const int tid = threadIdx.x;
    const int w = tid >> 5;
    const int wm = w & 1;
    const int wn = w >> 1;

    const size_t zb = (size_t)z * Sc * 64;

#pragma unroll
    for (int i = tid; i < 512; i += 256) {
        int r = i >> 3, c = (i & 7) * 8;
        *(uint4*)&Qhi[r * LDT + c] = *(const uint4*)&Qh[zb + (size_t)(q0 + r) * 64 + c];
        *(uint4*)&Qlo[r * LDT + c] = *(const uint4*)&Ql[zb + (size_t)(q0 + r) * 64 + c];
        *(uint4*)&Khi[r * LDT + c] = *(const uint4*)&Kh[zb + (size_t)(k0 + r) * 64 + c];
        *(uint4*)&Klo[r * LDT + c] = *(const uint4*)&Kl[zb + (size_t)(k0 + r) * 64 + c];
    }
    __syncthreads();

    bfrag_c acc[2];
    wmma::fill_fragment(acc[0], 0.0f);
    wmma::fill_fragment(acc[1], 0.0f);

#pragma unroll
    for (int ks = 0; ks < 4; ks++) {
        const int kb = ks * 16;
        bfrag_a fah[2], fal[2];
#pragma unroll
        for (int ti = 0; ti < 2; ti++) {
            wmma::load_matrix_sync(fah[ti], Qhi + (wm * 32 + ti * 16) * LDT + kb, LDT);
            wmma::load_matrix_sync(fal[ti], Qlo + (wm * 32 + ti * 16) * LDT + kb, LDT);
        }
        bfrag_bc fbh, fbl;
        wmma::load_matrix_sync(fbh, Khi + (wn * 16) * LDT + kb, LDT);
        wmma::load_matrix_sync(fbl, Klo + (wn * 16) * LDT + kb, LDT);
#pragma unroll
        for (int ti = 0; ti < 2; ti++) {
            wmma::mma_sync(acc[ti], fah[ti], fbh, acc[ti]);
            wmma::mma_sync(acc[ti], fah[ti], fbl, acc[ti]);
            wmma::mma_sync(acc[ti], fal[ti], fbh, acc[ti]);
        }
    }
    __syncthreads();
#pragma unroll
    for (int ti = 0; ti < 2; ti++)
        wmma::store_matrix_sync(&stg[(wm * 32 + ti * 16) * LDST + wn * 16], acc[ti],
                                LDST, wmma::mem_row_major);
    __syncthreads();

    const int mode = g_mask_mode;
    const int* mi = (const int*)mask;
    const unsigned char* mb8 = (const unsigned char*)mask;
    const float* mf = (const float*)mask;

#pragma unroll
    for (int i = tid; i < 4096; i += 256) {
        int r = i >> 6, c = i & 63;
        int qq = q0 + r, kk = k0 + c;
        size_t midx = (size_t)b * Sc * Sc + (size_t)qq * Sc + kk;
        bool masked;
        if (mode == 0)      masked = (mi[midx] != 0);
        else if (mode == 2) masked = (mf[midx] != 0.0f);
        else                masked = (mb8[midx] != 0);
        float v = masked ? -1e9f : stg[r * LDST + c] * 0.125f;
        attn[((size_t)z * Sc + qq) * Sc + kk] = v;
    }
}

// ---------------------------------------------------------------------------
// Row softmax, in place; also emits bf16 copy of probs for the context GEMM.
// ---------------------------------------------------------------------------
__global__ __launch_bounds__(256)
void softmax_kernel(float* __restrict__ attn, __nv_bfloat16* __restrict__ attn_bf) {
    const size_t row = blockIdx.x;
    float4* p = (float4*)(attn + row * Sc);
    __nv_bfloat16* pb = attn_bf + row * Sc;
    const int tid = threadIdx.x;
    const int lane = tid & 31, wid = tid >> 5;
    __shared__ float sm[16];

    float4 v = p[tid];
    float mx = fmaxf(fmaxf(v.x, v.y), fmaxf(v.z, v.w));
#pragma unroll
    for (int o = 16; o; o >>= 1) mx = fmaxf(mx, __shfl_xor_sync(0xffffffffu, mx, o));
    if (lane == 0) sm[wid] = mx;
    __syncthreads();
    float m = sm[0];
#pragma unroll
    for (int i = 1; i < 8; i++) m = fmaxf(m, sm[i]);

    v.x = expf(v.x - m); v.y = expf(v.y - m);
    v.z = expf(v.z - m); v.w = expf(v.w - m);
    float s = (v.x + v.y) + (v.z + v.w);
#pragma unroll
    for (int o = 16; o; o >>= 1) s += __shfl_xor_sync(0xffffffffu, s, o);
    if (lane == 0) sm[8 + wid] = s;
    __syncthreads();
    float tot = 0.0f;
#pragma unroll
    for (int i = 0; i < 8; i++) tot += sm[8 + i];
    float inv = 1.0f / tot;
    v.x *= inv; v.y *= inv; v.z *= inv; v.w *= inv;
    p[tid] = v;
    cvt_store4_s(pb + tid * 4, v);
}

// ---------------------------------------------------------------------------
// Context: BM=256, BN=64, single bf16, A = bf16 probs, warp tile 32x64.
// Out: bf16 ctx plane, concat layout [B,S,1024].
// ---------------------------------------------------------------------------
__global__ __launch_bounds__(256)
void context_wide(const __nv_bfloat16* __restrict__ P, const __nv_bfloat16* __restrict__ Vp,
                  __nv_bfloat16* __restrict__ C) {
    constexpr int LDA = 24;
    constexpr int LDW = 72;
    constexpr int LDST = 68;

    __shared__ __align__(16) char buf[34816];
    __nv_bfloat16* As = (__nv_bfloat16*)buf;         // [2][256][24]
    __nv_bfloat16* Ws = As + 2 * 256 * LDA;          // [2][16][72]
    float* stg = (float*)buf;                        // [128][68]

    const int tid = threadIdx.x;
    const int w = tid >> 5;                          // wm 0..7
    const int z = blockIdx.y;
    const int row0 = blockIdx.x * 256;

    const __nv_bfloat16* Pb = P + (size_t)z * Sc * Sc;
    const __nv_bfloat16* Vb = Vp + (size_t)z * Sc * 64;

    const int ar = tid >> 1, ac = (tid & 1) * 8;     // 2 rows-worth: ar, ar+128
    const int in_b = tid < 128;
    const int wr = tid >> 3, wc = (tid & 7) * 8;     // B: tid<128 only

    bfrag_c acc[2][4];
#pragma unroll
    for (int ti = 0; ti < 2; ti++)
#pragma unroll
        for (int tj = 0; tj < 4; tj++) wmma::fill_fragment(acc[ti][tj], 0.0f);

    uint4 pa0, pa1, pb;
    pa0 = *(const uint4*)&Pb[(size_t)(row0 + ar) * Sc + ac];
    pa1 = *(const uint4*)&Pb[(size_t)(row0 + ar + 128) * Sc + ac];
    if (in_b) pb = *(const uint4*)&Vb[(size_t)wr * 64 + wc];
    *(uint4*)&As[ar * LDA + ac] = pa0;
    *(uint4*)&As[(ar + 128) * LDA + ac] = pa1;
    if (in_b) *(uint4*)&Ws[wr * LDW + wc] = pb;
    __syncthreads();

    for (int kt = 0; kt < 64; kt++) {
        if (kt < 63) {
            int k = (kt + 1) * 16;
            pa0 = *(const uint4*)&Pb[(size_t)(row0 + ar) * Sc + k + ac];
            pa1 = *(const uint4*)&Pb[(size_t)(row0 + ar + 128) * Sc + k + ac];
            if (in_b) pb = *(const uint4*)&Vb[(size_t)(k + wr) * 64 + wc];
        }
        const int cur = kt & 1;
        const int cb = cur * 256 * LDA;
        const int wb = cur * 16 * LDW;

        bfrag_a fa[2];
#pragma unroll
        for (int ti = 0; ti < 2; ti++)
            wmma::load_matrix_sync(fa[ti], As + cb + (w * 32 + ti * 16) * LDA, LDA);
#pragma unroll
        for (int tj = 0; tj < 4; tj++) {
            bfrag_b fb;
            wmma::load_matrix_sync(fb, Ws + wb + tj * 16, LDW);
#pragma unroll
            for (int ti = 0; ti < 2; ti++)
                wmma::mma_sync(acc[ti][tj], fa[ti], fb, acc[ti][tj]);
        }

        if (kt < 63) {
            const int nb = (cur ^ 1) * 256 * LDA;
            const int nw = (cur ^ 1) * 16 * LDW;
            *(uint4*)&As[nb + ar * LDA + ac] = pa0;
            *(uint4*)&As[nb + (ar + 128) * LDA + ac] = pa1;
            if (in_b) *(uint4*)&Ws[nw + wr * LDW + wc] = pb;
        }
        __syncthreads();
    }

    const int b = z >> 4, h = z & 15;
#pragma unroll
    for (int ph = 0; ph < 2; ph++) {
        if ((w >> 2) == ph) {
#pragma unroll
            for (int ti = 0; ti < 2; ti++)
#pragma unroll
                for (int tj = 0; tj < 4; tj++)
                    wmma::store_matrix_sync(&stg[((w & 3) * 32 + ti * 16) * LDST + tj * 16],
                                            acc[ti][tj], LDST, wmma::mem_row_major);
        }
        __syncthreads();
#pragma unroll
        for (int i = tid; i < 2048; i += 256) {
            int r = i >> 4, c4 = (i & 15) * 4;
            int s = row0 + ph * 128 + r;
            float4 v = *(float4*)&stg[r * LDST + c4];
            cvt_store4_s(C + ((size_t)(b * Sc + s)) * HDc + h * DVc + c4, v);
        }
        __syncthreads();
    }
}

// ---------------------------------------------------------------------------
// Fused residual add + LayerNorm
// ---------------------------------------------------------------------------
__global__ __launch_bounds__(256)
void layernorm_kernel(const float* __restrict__ x, const float* __restrict__ resid,
                      float* __restrict__ out) {
    const size_t row = blockIdx.x;
    const float4* xr = (const float4*)(x + row * Dc);
    const float4* rr = (const float4*)(resid + row * Dc);
    float4* orow = (float4*)(out + row * Dc);
    const int tid = threadIdx.x;
    const int lane = tid & 31, wid = tid >> 5;
    __shared__ float sm[16];

    float4 a = xr[tid], b = rr[tid];
    float4 v = make_float4(a.x + b.x, a.y + b.y, a.z + b.z, a.w + b.w);
    float s = (v.x + v.y) + (v.z + v.w);
#pragma unroll
    for (int o = 16; o; o >>= 1) s += __shfl_xor_sync(0xffffffffu, s, o);
    if (lane == 0) sm[wid] = s;
    __syncthreads();
    float tot = 0.0f;
#pragma unroll
    for (int i = 0; i < 8; i++) tot += sm[i];
    float mean = tot * (1.0f / 1024.0f);

    float dx = v.x - mean, dy = v.y - mean, dz = v.z - mean, dw = v.w - mean;
    float vs = (dx * dx + dy * dy) + (dz * dz + dw * dw);
#pragma unroll
    for (int o = 16; o; o >>= 1) vs += __shfl_xor_sync(0xffffffffu, vs, o);
    if (lane == 0) sm[8 + wid] = vs;
    __syncthreads();
    float vtot = 0.0f;
#pragma unroll
    for (int i = 0; i < 8; i++) vtot += sm[8 + i];
    float inv = rsqrtf(vtot * (1.0f / 1024.0f) + 1e-5f);
    orow[tid] = make_float4(dx * inv, dy * inv, dz * inv, dw * inv);
}

// ---------------------------------------------------------------------------
// Launch
// ---------------------------------------------------------------------------
extern "C" void kernel_launch(void* const* d_in, const int* in_sizes, int n_in,
                              void* d_out, int out_size) {
    const float* q    = (const float*)d_in[0];
    const float* k    = (const float*)d_in[1];
    const float* v    = (const float*)d_in[2];
    const void*  mask = d_in[3];
    const float* Wq   = (const float*)d_in[4];
    const float* bq   = (const float*)d_in[5];
    const float* Wk   = (const float*)d_in[6];
    const float* bk   = (const float*)d_in[7];
    const float* Wv   = (const float*)d_in[8];
    const float* bv   = (const float*)d_in[9];
    const float* Wo   = (const float*)d_in[10];
    const float* bo   = (const float*)d_in[11];
    float* out = (float*)d_out;

    __nv_bfloat16 *Qph, *Qpl, *Kph, *Kpl, *Vp, *ctx, *attn_bf;
    float *obuf, *attn_fb;
    cudaGetSymbolAddress((void**)&Qph, g_Qph); cudaGetSymbolAddress((void**)&Qpl, g_Qpl);
    cudaGetSymbolAddress((void**)&Kph, g_Kph); cudaGetSymbolAddress((void**)&Kpl, g_Kpl);
    cudaGetSymbolAddress((void**)&Vp, g_Vp);
    cudaGetSymbolAddress((void**)&ctx, g_ctx);
    cudaGetSymbolAddress((void**)&attn_bf, g_attn_bf);
    cudaGetSymbolAddress((void**)&obuf, g_obuf);
    cudaGetSymbolAddress((void**)&attn_fb, g_attn_fb);

    const long long LN_ELEMS = (long long)Mc * Dc;
    const long long ATTN_ELEMS = (long long)Bc * Hc * Sc * Sc;
    float* attn = ((long long)out_size >= LN_ELEMS + ATTN_ELEMS)
                      ? (out + (size_t)LN_ELEMS)
                      : attn_fb;

    detect_mask_kernel<<<1, 1>>>((const unsigned int*)mask);

    // Q/K projections: split-bf16, wide tiles, hi/lo plane output
    proj_split_wide<<<dim3(8, 32), 256>>>(q, Wq, bq, Qph, Qpl);
    proj_split_wide<<<dim3(8, 32), 256>>>(k, Wk, bk, Kph, Kpl);
    // V projection: single-bf16, wide
    gemm_single_wide<1, 1><<<dim3(8, 32), 256>>>(v, Wv, bv, nullptr, Vp);

    // Scores + mask -> raw scores
    scores_planes<<<dim3(16, 16, Bc * Hc), 256>>>(Qph, Qpl, Kph, Kpl, mask, attn);

    // Softmax in place + bf16 probs copy
    softmax_kernel<<<Bc * Hc * Sc, 256>>>(attn, attn_bf);

    // Context (bf16 probs, wide) -> ctx bf16 plane
    context_wide<<<dim3(4, 64), 256>>>(attn_bf, Vp, ctx);

    // Output projection (bf16 A, wide, fp32 out)
    gemm_single_wide<0, 0><<<dim3(8, 32), 256>>>(ctx, Wo, bo, obuf, nullptr);

    // Residual + LayerNorm
    layernorm_kernel<<<Mc, 256>>>(obuf, q, out);
}